// round 4
// baseline (speedup 1.0000x reference)
#include <cuda_runtime.h>

// Problem constants (fixed by the dataset)
#define U_N 200000
#define M_N 100000
#define E_MAX 2000000
#define HD 64
#define CD 7

// ---------------- scratch (device globals; no allocation allowed) ----------------
__device__ float g_xmovie[M_N * HD];
__device__ float g_agg_u[U_N * HD];
__device__ float g_agg_m[M_N * HD];
__device__ float g_u1[U_N * HD];
__device__ float g_m1[M_N * HD];
__device__ float g_u2[U_N * HD];
__device__ float g_m2[M_N * HD];
__device__ float g_proj_u[U_N * CD];
__device__ float g_proj_m[M_N * CD];

__device__ int g_deg_u[U_N];
__device__ int g_off_u[U_N + 1];
__device__ int g_cur_u[U_N];
__device__ int g_deg_m[M_N];
__device__ int g_off_m[M_N + 1];
__device__ int g_cur_m[M_N];
__device__ int g_nbr_u[E_MAX];   // movie neighbor per user-grouped edge
__device__ int g_nbr_m[E_MAX];   // user neighbor per movie-grouped edge
__device__ int g_mode[4];        // 1 => indices are int64 on disk, 0 => int32

// ---------------- helpers ----------------
__device__ __forceinline__ int ld_idx(const int* __restrict__ p, int i, int m64) {
    // little-endian int64 with small nonnegative values: low word is the value
    return m64 ? p[2 * i] : p[i];
}

// detect int32 vs int64 for the 4 index arrays: odd 32-bit words all zero => int64
__global__ void detect_kernel(const int* es, const int* ed, const int* ls, const int* ld_) {
    int t = threadIdx.x;
    if (t < 4) {
        const int* p = (t == 0) ? es : (t == 1) ? ed : (t == 2) ? ls : ld_;
        int o = 0;
#pragma unroll
        for (int i = 0; i < 64; i++) o |= p[2 * i + 1];
        g_mode[t] = (o == 0) ? 1 : 0;
    }
}

// ---------------- x_movie = movie_x @ w_movie + b_movie + movie_emb ----------------
__global__ void xmovie_kernel(const float* __restrict__ mx, const float* __restrict__ w,
                              const float* __restrict__ b, const float* __restrict__ emb) {
    int idx = blockIdx.x * blockDim.x + threadIdx.x;
    if (idx >= M_N * HD) return;
    int m = idx >> 6;
    int h = idx & 63;
    float acc = b[h] + emb[idx];
    const float* xr = mx + m * 20;
#pragma unroll
    for (int f = 0; f < 20; f++) acc = fmaf(xr[f], w[f * 64 + h], acc);
    g_xmovie[idx] = acc;
}

// ---------------- CSR build ----------------
__global__ void zero_deg_kernel() {
    int i = blockIdx.x * blockDim.x + threadIdx.x;
    if (i < U_N) g_deg_u[i] = 0;
    if (i < M_N) g_deg_m[i] = 0;
}

__global__ void hist_kernel(const int* __restrict__ es, const int* __restrict__ ed, int E) {
    int m0 = g_mode[0], m1 = g_mode[1];
    for (int i = blockIdx.x * blockDim.x + threadIdx.x; i < E; i += gridDim.x * blockDim.x) {
        atomicAdd(&g_deg_u[ld_idx(es, i, m0)], 1);
        atomicAdd(&g_deg_m[ld_idx(ed, i, m1)], 1);
    }
}

// single-block exclusive scan; also writes cursor copy and off[n] = total
__global__ void scan_kernel(const int* __restrict__ deg, int* __restrict__ off,
                            int* __restrict__ cur, int n) {
    __shared__ int sh[1024];
    int tid = threadIdx.x;
    int chunk = (n + 1023) >> 10;
    int s0 = tid * chunk;
    int s1 = min(s0 + chunk, n);
    int sum = 0;
    for (int i = s0; i < s1; i++) sum += deg[i];
    sh[tid] = sum;
    __syncthreads();
    for (int d = 1; d < 1024; d <<= 1) {
        int v = (tid >= d) ? sh[tid - d] : 0;
        __syncthreads();
        sh[tid] += v;
        __syncthreads();
    }
    int run = (tid == 0) ? 0 : sh[tid - 1];
    for (int i = s0; i < s1; i++) {
        off[i] = run;
        cur[i] = run;
        run += deg[i];
    }
    if (tid == 0) off[n] = sh[1023];
}

__global__ void fill_kernel(const int* __restrict__ es, const int* __restrict__ ed, int E) {
    int m0 = g_mode[0], m1 = g_mode[1];
    for (int i = blockIdx.x * blockDim.x + threadIdx.x; i < E; i += gridDim.x * blockDim.x) {
        int s = ld_idx(es, i, m0);
        int d = ld_idx(ed, i, m1);
        int pu = atomicAdd(&g_cur_u[s], 1);
        g_nbr_u[pu] = d;
        int pm = atomicAdd(&g_cur_m[d], 1);
        g_nbr_m[pm] = s;
    }
}

// ---------------- mean aggregation: out[node] = mean over nbr of x[nbr] ----------------
__global__ void agg_kernel(const float* __restrict__ x, const int* __restrict__ off,
                           const int* __restrict__ nbr, float* __restrict__ out, int N) {
    int node = blockIdx.x * 4 + (threadIdx.x >> 6);
    int t = threadIdx.x & 63;
    if (node >= N) return;
    int s = off[node];
    int e = off[node + 1];
    float acc0 = 0.f, acc1 = 0.f;
    int j = s;
    for (; j + 1 < e; j += 2) {
        int n0 = __ldg(&nbr[j]);
        int n1 = __ldg(&nbr[j + 1]);
        acc0 += x[n0 * 64 + t];
        acc1 += x[n1 * 64 + t];
    }
    if (j < e) acc0 += x[__ldg(&nbr[j]) * 64 + t];
    float inv = 1.0f / (float)max(e - s, 1);
    out[node * 64 + t] = (acc0 + acc1) * inv;
}

// ---------------- fused SAGE linear: O = act(A@Wl + X@Wr + b) ----------------
// tile: 64 rows x 64 cols, 256 threads, 4x4 register tile per thread
__global__ void gemm64_kernel(const float* __restrict__ A, const float* __restrict__ X,
                              const float* __restrict__ Wl, const float* __restrict__ Wr,
                              const float* __restrict__ bias, float* __restrict__ O,
                              int N, int do_relu) {
    extern __shared__ float sh[];
    float* sWl = sh;                 // 64*64
    float* sWr = sh + 4096;         // 64*64
    float* sA = sh + 8192;          // 64*65 (padded)
    float* sX = sA + 64 * 65;       // 64*65 (padded)
    int tid = threadIdx.x;
    int nb = blockIdx.x * 64;

    {
        const float4* wl4 = (const float4*)Wl;
        const float4* wr4 = (const float4*)Wr;
        float4* sl = (float4*)sWl;
        float4* sr = (float4*)sWr;
#pragma unroll
        for (int i = 0; i < 4; i++) {
            sl[tid + 256 * i] = wl4[tid + 256 * i];
            sr[tid + 256 * i] = wr4[tid + 256 * i];
        }
    }
#pragma unroll
    for (int i = 0; i < 4; i++) {
        int f = tid + 256 * i;       // float4 slot id, 0..1023
        int r = f >> 4;              // row 0..63
        int cc = f & 15;             // float4 col 0..15
        int gr = nb + r;
        float4 va = make_float4(0.f, 0.f, 0.f, 0.f);
        float4 vx = va;
        if (gr < N) {
            va = ((const float4*)A)[gr * 16 + cc];
            vx = ((const float4*)X)[gr * 16 + cc];
        }
        float* pa = &sA[r * 65 + cc * 4];
        pa[0] = va.x; pa[1] = va.y; pa[2] = va.z; pa[3] = va.w;
        float* px = &sX[r * 65 + cc * 4];
        px[0] = vx.x; px[1] = vx.y; px[2] = vx.z; px[3] = vx.w;
    }
    __syncthreads();

    int ty = tid >> 4, tx = tid & 15;
    int r0 = ty * 4, c0 = tx * 4;
    float acc[4][4];
#pragma unroll
    for (int i = 0; i < 4; i++)
#pragma unroll
        for (int jj = 0; jj < 4; jj++) acc[i][jj] = 0.f;

#pragma unroll 16
    for (int k = 0; k < 64; k++) {
        float4 wl = *(const float4*)&sWl[k * 64 + c0];
        float4 wr = *(const float4*)&sWr[k * 64 + c0];
#pragma unroll
        for (int i = 0; i < 4; i++) {
            float a = sA[(r0 + i) * 65 + k];
            float x = sX[(r0 + i) * 65 + k];
            acc[i][0] = fmaf(a, wl.x, fmaf(x, wr.x, acc[i][0]));
            acc[i][1] = fmaf(a, wl.y, fmaf(x, wr.y, acc[i][1]));
            acc[i][2] = fmaf(a, wl.z, fmaf(x, wr.z, acc[i][2]));
            acc[i][3] = fmaf(a, wl.w, fmaf(x, wr.w, acc[i][3]));
        }
    }

    float4 bv = *(const float4*)&bias[c0];
#pragma unroll
    for (int i = 0; i < 4; i++) {
        int gr = nb + r0 + i;
        if (gr < N) {
            float4 v;
            v.x = acc[i][0] + bv.x;
            v.y = acc[i][1] + bv.y;
            v.z = acc[i][2] + bv.z;
            v.w = acc[i][3] + bv.w;
            if (do_relu) {
                v.x = fmaxf(v.x, 0.f); v.y = fmaxf(v.y, 0.f);
                v.z = fmaxf(v.z, 0.f); v.w = fmaxf(v.w, 0.f);
            }
            *(float4*)&O[gr * 64 + c0] = v;
        }
    }
}

// ---------------- classifier projection: out = x @ W(64x7) [+ b] ----------------
__global__ void proj_kernel(const float* __restrict__ x, const float* __restrict__ W,
                            const float* __restrict__ b, float* __restrict__ out,
                            int N, int use_bias) {
    __shared__ float sX[32 * 64];
    __shared__ float sW[64 * 7];
    int tid = threadIdx.x;
    // FIX (round 3): block has 256 threads but 448 weights — must stride.
    for (int i = tid; i < 448; i += 256) sW[i] = W[i];
    int base = blockIdx.x * 32;
#pragma unroll
    for (int i = tid; i < 2048; i += 256) {
        int node = base + (i >> 6);
        sX[i] = (node < N) ? x[base * 64 + i] : 0.f;
    }
    __syncthreads();
    if (tid < 224) {
        int nl = tid / 7;
        int c = tid - nl * 7;
        int node = base + nl;
        if (node < N) {
            float acc = use_bias ? b[c] : 0.f;
#pragma unroll
            for (int k = 0; k < 64; k++) acc = fmaf(sX[nl * 64 + k], sW[k * 7 + c], acc);
            out[node * 7 + c] = acc;
        }
    }
}

// ---------------- final edge output: out[e][c] = proj_u[src][c] + proj_m[dst][c] ----------------
__global__ void final_kernel(const int* __restrict__ ls, const int* __restrict__ ld_,
                             float* __restrict__ out, int EL) {
    int m2 = g_mode[2], m3 = g_mode[3];
    int total = EL * 7;
    for (int idx = blockIdx.x * blockDim.x + threadIdx.x; idx < total;
         idx += gridDim.x * blockDim.x) {
        int e = idx / 7;
        int c = idx - e * 7;
        int s = ld_idx(ls, e, m2);
        int d = ld_idx(ld_, e, m3);
        out[idx] = g_proj_u[s * 7 + c] + g_proj_m[d * 7 + c];
    }
}

// ---------------- launch ----------------
extern "C" void kernel_launch(void* const* d_in, const int* in_sizes, int n_in,
                              void* d_out, int out_size) {
    const float* movie_x = (const float*)d_in[2];
    const int* edge_src = (const int*)d_in[3];
    const int* edge_dst = (const int*)d_in[4];
    const int* el_src = (const int*)d_in[5];
    const int* el_dst = (const int*)d_in[6];
    const float* user_emb = (const float*)d_in[7];
    const float* movie_emb = (const float*)d_in[8];
    const float* w_movie = (const float*)d_in[9];
    const float* b_movie = (const float*)d_in[10];
    const float* l1_rates_Wl = (const float*)d_in[11];
    const float* l1_rates_bl = (const float*)d_in[12];
    const float* l1_rates_Wr = (const float*)d_in[13];
    const float* l1_rev_Wl = (const float*)d_in[14];
    const float* l1_rev_bl = (const float*)d_in[15];
    const float* l1_rev_Wr = (const float*)d_in[16];
    const float* l2_rates_Wl = (const float*)d_in[17];
    const float* l2_rates_bl = (const float*)d_in[18];
    const float* l2_rates_Wr = (const float*)d_in[19];
    const float* l2_rev_Wl = (const float*)d_in[20];
    const float* l2_rev_bl = (const float*)d_in[21];
    const float* l2_rev_Wr = (const float*)d_in[22];
    const float* cls_W = (const float*)d_in[23];
    const float* cls_b = (const float*)d_in[24];
    float* out = (float*)d_out;

    int E = in_sizes[3];
    if (E > E_MAX) E = E_MAX;
    int EL = out_size / 7;

    // device symbol addresses for reusable buffers
    float *p_xmovie, *p_agg_u, *p_agg_m, *p_u1, *p_m1, *p_u2, *p_m2, *p_pu, *p_pm;
    int *p_deg_u, *p_off_u, *p_cur_u, *p_deg_m, *p_off_m, *p_cur_m, *p_nbr_u, *p_nbr_m;
    cudaGetSymbolAddress((void**)&p_xmovie, g_xmovie);
    cudaGetSymbolAddress((void**)&p_agg_u, g_agg_u);
    cudaGetSymbolAddress((void**)&p_agg_m, g_agg_m);
    cudaGetSymbolAddress((void**)&p_u1, g_u1);
    cudaGetSymbolAddress((void**)&p_m1, g_m1);
    cudaGetSymbolAddress((void**)&p_u2, g_u2);
    cudaGetSymbolAddress((void**)&p_m2, g_m2);
    cudaGetSymbolAddress((void**)&p_pu, g_proj_u);
    cudaGetSymbolAddress((void**)&p_pm, g_proj_m);
    cudaGetSymbolAddress((void**)&p_deg_u, g_deg_u);
    cudaGetSymbolAddress((void**)&p_off_u, g_off_u);
    cudaGetSymbolAddress((void**)&p_cur_u, g_cur_u);
    cudaGetSymbolAddress((void**)&p_deg_m, g_deg_m);
    cudaGetSymbolAddress((void**)&p_off_m, g_off_m);
    cudaGetSymbolAddress((void**)&p_cur_m, g_cur_m);
    cudaGetSymbolAddress((void**)&p_nbr_u, g_nbr_u);
    cudaGetSymbolAddress((void**)&p_nbr_m, g_nbr_m);

    const int SMEM = (8192 + 2 * 64 * 65) * 4;  // 66048 bytes
    cudaFuncSetAttribute(gemm64_kernel, cudaFuncAttributeMaxDynamicSharedMemorySize, SMEM);

    // 0. index dtype detection
    detect_kernel<<<1, 32>>>(edge_src, edge_dst, el_src, el_dst);

    // 1. movie input projection
    xmovie_kernel<<<(M_N * HD + 255) / 256, 256>>>(movie_x, w_movie, b_movie, movie_emb);

    // 2. CSR build (both directions)
    zero_deg_kernel<<<(U_N + 255) / 256, 256>>>();
    hist_kernel<<<1184, 256>>>(edge_src, edge_dst, E);
    scan_kernel<<<1, 1024>>>(p_deg_u, p_off_u, p_cur_u, U_N);
    scan_kernel<<<1, 1024>>>(p_deg_m, p_off_m, p_cur_m, M_N);
    fill_kernel<<<1184, 256>>>(edge_src, edge_dst, E);

    // 3. layer 1
    agg_kernel<<<(U_N + 3) / 4, 256>>>(p_xmovie, p_off_u, p_nbr_u, p_agg_u, U_N);
    gemm64_kernel<<<(U_N + 63) / 64, 256, SMEM>>>(p_agg_u, user_emb, l1_rev_Wl, l1_rev_Wr,
                                                  l1_rev_bl, p_u1, U_N, 1);
    agg_kernel<<<(M_N + 3) / 4, 256>>>(user_emb, p_off_m, p_nbr_m, p_agg_m, M_N);
    gemm64_kernel<<<(M_N + 63) / 64, 256, SMEM>>>(p_agg_m, p_xmovie, l1_rates_Wl, l1_rates_Wr,
                                                  l1_rates_bl, p_m1, M_N, 1);

    // 4. layer 2
    agg_kernel<<<(U_N + 3) / 4, 256>>>(p_m1, p_off_u, p_nbr_u, p_agg_u, U_N);
    gemm64_kernel<<<(U_N + 63) / 64, 256, SMEM>>>(p_agg_u, p_u1, l2_rev_Wl, l2_rev_Wr,
                                                  l2_rev_bl, p_u2, U_N, 0);
    agg_kernel<<<(M_N + 3) / 4, 256>>>(p_u1, p_off_m, p_nbr_m, p_agg_m, M_N);
    gemm64_kernel<<<(M_N + 63) / 64, 256, SMEM>>>(p_agg_m, p_m1, l2_rates_Wl, l2_rates_Wr,
                                                  l2_rates_bl, p_m2, M_N, 0);

    // 5. classifier split into per-node projections + per-edge gather-add
    proj_kernel<<<(U_N + 31) / 32, 256>>>(p_u2, cls_W, cls_b, p_pu, U_N, 0);
    proj_kernel<<<(M_N + 31) / 32, 256>>>(p_m2, cls_W + 64 * CD, cls_b, p_pm, M_N, 1);
    final_kernel<<<(EL * 7 + 255) / 256, 256>>>(el_src, el_dst, out, EL);
}

// round 6
// speedup vs baseline: 1.1363x; 1.1363x over previous
#include <cuda_runtime.h>

// Problem constants (fixed by the dataset)
#define U_N 200000
#define M_N 100000
#define E_MAX 2000000
#define HD 64
#define CD 7

// ---------------- scratch (device globals; no allocation allowed) ----------------
__device__ float g_xmovie[M_N * HD];
__device__ float g_u1[U_N * HD];
__device__ float g_m1[M_N * HD];
__device__ float g_proj_u[U_N * CD];
__device__ float g_proj_m[M_N * CD];

__device__ int g_deg_u[U_N];
__device__ int g_off_u[U_N + 1];
__device__ int g_cur_u[U_N];
__device__ int g_deg_m[M_N];
__device__ int g_off_m[M_N + 1];
__device__ int g_cur_m[M_N];
__device__ int g_nbr_u[E_MAX];   // movie neighbor per user-grouped edge
__device__ int g_nbr_m[E_MAX];   // user neighbor per movie-grouped edge
__device__ int g_mode[4];        // 1 => indices are int64 on disk, 0 => int32

// ---------------- helpers ----------------
__device__ __forceinline__ int ld_idx(const int* __restrict__ p, int i, int m64) {
    // little-endian int64 with small nonnegative values: low word is the value
    return m64 ? p[2 * i] : p[i];
}

// detect int32 vs int64 for the 4 index arrays: odd 32-bit words all zero => int64
__global__ void detect_kernel(const int* es, const int* ed, const int* ls, const int* ld_) {
    int t = threadIdx.x;
    if (t < 4) {
        const int* p = (t == 0) ? es : (t == 1) ? ed : (t == 2) ? ls : ld_;
        int o = 0;
#pragma unroll
        for (int i = 0; i < 64; i++) o |= p[2 * i + 1];
        g_mode[t] = (o == 0) ? 1 : 0;
    }
}

// ---------------- x_movie = movie_x @ w_movie + b_movie + movie_emb ----------------
__global__ void xmovie_kernel(const float* __restrict__ mx, const float* __restrict__ w,
                              const float* __restrict__ b, const float* __restrict__ emb) {
    int idx = blockIdx.x * blockDim.x + threadIdx.x;
    if (idx >= M_N * HD) return;
    int m = idx >> 6;
    int h = idx & 63;
    float acc = b[h] + emb[idx];
    const float* xr = mx + m * 20;
#pragma unroll
    for (int f = 0; f < 20; f++) acc = fmaf(xr[f], w[f * 64 + h], acc);
    g_xmovie[idx] = acc;
}

// ---------------- CSR build ----------------
__global__ void zero_deg_kernel() {
    int i = blockIdx.x * blockDim.x + threadIdx.x;
    if (i < U_N) g_deg_u[i] = 0;
    if (i < M_N) g_deg_m[i] = 0;
}

__global__ void hist_kernel(const int* __restrict__ es, const int* __restrict__ ed, int E) {
    int m0 = g_mode[0], m1 = g_mode[1];
    for (int i = blockIdx.x * blockDim.x + threadIdx.x; i < E; i += gridDim.x * blockDim.x) {
        atomicAdd(&g_deg_u[ld_idx(es, i, m0)], 1);
        atomicAdd(&g_deg_m[ld_idx(ed, i, m1)], 1);
    }
}

// single-block exclusive scan body; also writes cursor copy and off[n] = total
__device__ void scan_body(const int* __restrict__ deg, int* __restrict__ off,
                          int* __restrict__ cur, int n) {
    __shared__ int sh[1024];
    int tid = threadIdx.x;
    int chunk = (n + 1023) >> 10;
    int s0 = tid * chunk;
    int s1 = min(s0 + chunk, n);
    int sum = 0;
    for (int i = s0; i < s1; i++) sum += deg[i];
    sh[tid] = sum;
    __syncthreads();
    for (int d = 1; d < 1024; d <<= 1) {
        int v = (tid >= d) ? sh[tid - d] : 0;
        __syncthreads();
        sh[tid] += v;
        __syncthreads();
    }
    int run = (tid == 0) ? 0 : sh[tid - 1];
    for (int i = s0; i < s1; i++) {
        off[i] = run;
        cur[i] = run;
        run += deg[i];
    }
    if (tid == 0) off[n] = sh[1023];
}

// block 0 scans user degrees, block 1 scans movie degrees (parallel on 2 SMs)
__global__ void scan_both_kernel() {
    if (blockIdx.x == 0) scan_body(g_deg_u, g_off_u, g_cur_u, U_N);
    else                 scan_body(g_deg_m, g_off_m, g_cur_m, M_N);
}

__global__ void fill_kernel(const int* __restrict__ es, const int* __restrict__ ed, int E) {
    int m0 = g_mode[0], m1 = g_mode[1];
    for (int i = blockIdx.x * blockDim.x + threadIdx.x; i < E; i += gridDim.x * blockDim.x) {
        int s = ld_idx(es, i, m0);
        int d = ld_idx(ed, i, m1);
        int pu = atomicAdd(&g_cur_u[s], 1);
        g_nbr_u[pu] = d;
        int pm = atomicAdd(&g_cur_m[d], 1);
        g_nbr_m[pm] = s;
    }
}

// ---------------- fused SAGE layer: O = act(mean_agg(xsrc)@Wl + Xroot@Wr + b) ----------------
// One block = 64 nodes x 64 out-cols. Aggregation is done in-block (warp per node,
// float2 lanes) straight into the smem A tile — no intermediate agg buffer.
// If `proj` is non-null the 64x64 output tile is NOT stored; instead it is projected
// through clsW (64x7) [+ clsb] and written to proj (layer-2 + classifier fusion).
#define ROWSTRIDE 66
__global__ void sage_fused_kernel(const float* __restrict__ xsrc, const float* __restrict__ Xroot,
                                  const int* __restrict__ off, const int* __restrict__ nbr,
                                  const float* __restrict__ Wl, const float* __restrict__ Wr,
                                  const float* __restrict__ bias, float* __restrict__ O,
                                  int N, int do_relu,
                                  const float* __restrict__ clsW, const float* __restrict__ clsb,
                                  float* __restrict__ proj, int use_cls_bias) {
    extern __shared__ float sh[];
    float* sWl = sh;                       // 64*64
    float* sWr = sh + 4096;                // 64*64
    float* sA  = sh + 8192;                // 64*66 (padded, float2-aligned rows)
    float* sX  = sA + 64 * ROWSTRIDE;      // 64*66
    int tid = threadIdx.x;
    int nb = blockIdx.x * 64;

    // weights -> smem (coalesced float4)
    {
        const float4* wl4 = (const float4*)Wl;
        const float4* wr4 = (const float4*)Wr;
        float4* sl = (float4*)sWl;
        float4* sr = (float4*)sWr;
#pragma unroll
        for (int i = 0; i < 4; i++) {
            sl[tid + 256 * i] = wl4[tid + 256 * i];
            sr[tid + 256 * i] = wr4[tid + 256 * i];
        }
    }

    // ---- fused mean aggregation: warp per node, 8 rounds, float2 per lane ----
    {
        int warp = tid >> 5;
        int lane = tid & 31;
#pragma unroll
        for (int it = 0; it < 8; it++) {
            int r = warp * 8 + it;
            int node = nb + r;
            float a0 = 0.f, a1 = 0.f;
            if (node < N) {
                int s = __ldg(&off[node]);
                int e = __ldg(&off[node + 1]);
                int j = s;
                for (; j + 4 <= e; j += 4) {
                    int n0 = __ldg(&nbr[j]);
                    int n1 = __ldg(&nbr[j + 1]);
                    int n2 = __ldg(&nbr[j + 2]);
                    int n3 = __ldg(&nbr[j + 3]);
                    float2 v0 = ((const float2*)(xsrc + n0 * 64))[lane];
                    float2 v1 = ((const float2*)(xsrc + n1 * 64))[lane];
                    float2 v2 = ((const float2*)(xsrc + n2 * 64))[lane];
                    float2 v3 = ((const float2*)(xsrc + n3 * 64))[lane];
                    a0 += v0.x + v1.x + v2.x + v3.x;
                    a1 += v0.y + v1.y + v2.y + v3.y;
                }
                for (; j < e; j++) {
                    float2 v = ((const float2*)(xsrc + __ldg(&nbr[j]) * 64))[lane];
                    a0 += v.x;
                    a1 += v.y;
                }
                float inv = 1.0f / (float)max(e - s, 1);
                a0 *= inv;
                a1 *= inv;
            }
            *(float2*)&sA[r * ROWSTRIDE + lane * 2] = make_float2(a0, a1);
        }
    }

    // ---- root features -> smem (coalesced float4 from gmem) ----
#pragma unroll
    for (int i = 0; i < 4; i++) {
        int f = tid + 256 * i;       // float4 slot id, 0..1023
        int r = f >> 4;              // row 0..63
        int cc = f & 15;             // float4 col 0..15
        int gr = nb + r;
        float4 vx = make_float4(0.f, 0.f, 0.f, 0.f);
        if (gr < N) vx = ((const float4*)Xroot)[gr * 16 + cc];
        float* px = &sX[r * ROWSTRIDE + cc * 4];
        px[0] = vx.x; px[1] = vx.y; px[2] = vx.z; px[3] = vx.w;
    }
    __syncthreads();

    // ---- mainloop: 4x4 register tile, dual-weight FMA ----
    int ty = tid >> 4, tx = tid & 15;
    int r0 = ty * 4, c0 = tx * 4;
    float acc[4][4];
#pragma unroll
    for (int i = 0; i < 4; i++)
#pragma unroll
        for (int jj = 0; jj < 4; jj++) acc[i][jj] = 0.f;

#pragma unroll 16
    for (int k = 0; k < 64; k++) {
        float4 wl = *(const float4*)&sWl[k * 64 + c0];
        float4 wr = *(const float4*)&sWr[k * 64 + c0];
#pragma unroll
        for (int i = 0; i < 4; i++) {
            float a = sA[(r0 + i) * ROWSTRIDE + k];
            float x = sX[(r0 + i) * ROWSTRIDE + k];
            acc[i][0] = fmaf(a, wl.x, fmaf(x, wr.x, acc[i][0]));
            acc[i][1] = fmaf(a, wl.y, fmaf(x, wr.y, acc[i][1]));
            acc[i][2] = fmaf(a, wl.z, fmaf(x, wr.z, acc[i][2]));
            acc[i][3] = fmaf(a, wl.w, fmaf(x, wr.w, acc[i][3]));
        }
    }

    float4 bv = *(const float4*)&bias[c0];

    if (proj == nullptr) {
        // layer-1 epilogue: bias (+relu) -> gmem
#pragma unroll
        for (int i = 0; i < 4; i++) {
            int gr = nb + r0 + i;
            if (gr < N) {
                float4 v;
                v.x = acc[i][0] + bv.x;
                v.y = acc[i][1] + bv.y;
                v.z = acc[i][2] + bv.z;
                v.w = acc[i][3] + bv.w;
                if (do_relu) {
                    v.x = fmaxf(v.x, 0.f); v.y = fmaxf(v.y, 0.f);
                    v.z = fmaxf(v.z, 0.f); v.w = fmaxf(v.w, 0.f);
                }
                *(float4*)&O[gr * 64 + c0] = v;
            }
        }
    } else {
        // layer-2 epilogue: biased tile -> smem, then fused 64->7 classifier projection.
        __syncthreads();   // mainloop reads of sA done before overwrite
#pragma unroll
        for (int i = 0; i < 4; i++) {
            float* p = &sA[(r0 + i) * ROWSTRIDE + c0];
            *(float2*)&p[0] = make_float2(acc[i][0] + bv.x, acc[i][1] + bv.y);
            *(float2*)&p[2] = make_float2(acc[i][2] + bv.z, acc[i][3] + bv.w);
        }
        // classifier weights (64x7) into sWl region
        for (int i = tid; i < 448; i += 256) sWl[i] = clsW[i];
        __syncthreads();
        for (int o = tid; o < 448; o += 256) {
            int nl = o / 7;
            int c = o - nl * 7;
            int gr = nb + nl;
            if (gr < N) {
                float pacc = use_cls_bias ? clsb[c] : 0.f;
#pragma unroll
                for (int k = 0; k < 64; k++)
                    pacc = fmaf(sA[nl * ROWSTRIDE + k], sWl[k * 7 + c], pacc);
                proj[gr * 7 + c] = pacc;
            }
        }
    }
}

// ---------------- final edge output: out[e][c] = proj_u[src][c] + proj_m[dst][c] ----------------
__global__ void final_kernel(const int* __restrict__ ls, const int* __restrict__ ld_,
                             float* __restrict__ out, int EL) {
    int m2 = g_mode[2], m3 = g_mode[3];
    int total = EL * 7;
    for (int idx = blockIdx.x * blockDim.x + threadIdx.x; idx < total;
         idx += gridDim.x * blockDim.x) {
        int e = idx / 7;
        int c = idx - e * 7;
        int s = ld_idx(ls, e, m2);
        int d = ld_idx(ld_, e, m3);
        out[idx] = g_proj_u[s * 7 + c] + g_proj_m[d * 7 + c];
    }
}

// ---------------- launch ----------------
extern "C" void kernel_launch(void* const* d_in, const int* in_sizes, int n_in,
                              void* d_out, int out_size) {
    const float* movie_x = (const float*)d_in[2];
    const int* edge_src = (const int*)d_in[3];
    const int* edge_dst = (const int*)d_in[4];
    const int* el_src = (const int*)d_in[5];
    const int* el_dst = (const int*)d_in[6];
    const float* user_emb = (const float*)d_in[7];
    const float* movie_emb = (const float*)d_in[8];
    const float* w_movie = (const float*)d_in[9];
    const float* b_movie = (const float*)d_in[10];
    const float* l1_rates_Wl = (const float*)d_in[11];
    const float* l1_rates_bl = (const float*)d_in[12];
    const float* l1_rates_Wr = (const float*)d_in[13];
    const float* l1_rev_Wl = (const float*)d_in[14];
    const float* l1_rev_bl = (const float*)d_in[15];
    const float* l1_rev_Wr = (const float*)d_in[16];
    const float* l2_rates_Wl = (const float*)d_in[17];
    const float* l2_rates_bl = (const float*)d_in[18];
    const float* l2_rates_Wr = (const float*)d_in[19];
    const float* l2_rev_Wl = (const float*)d_in[20];
    const float* l2_rev_bl = (const float*)d_in[21];
    const float* l2_rev_Wr = (const float*)d_in[22];
    const float* cls_W = (const float*)d_in[23];
    const float* cls_b = (const float*)d_in[24];
    float* out = (float*)d_out;

    int E = in_sizes[3];
    if (E > E_MAX) E = E_MAX;
    int EL = out_size / 7;

    // device symbol addresses for reusable buffers
    float *p_xmovie, *p_u1, *p_m1, *p_pu, *p_pm;
    int *p_off_u, *p_nbr_u, *p_off_m, *p_nbr_m;
    cudaGetSymbolAddress((void**)&p_xmovie, g_xmovie);
    cudaGetSymbolAddress((void**)&p_u1, g_u1);
    cudaGetSymbolAddress((void**)&p_m1, g_m1);
    cudaGetSymbolAddress((void**)&p_pu, g_proj_u);
    cudaGetSymbolAddress((void**)&p_pm, g_proj_m);
    cudaGetSymbolAddress((void**)&p_off_u, g_off_u);
    cudaGetSymbolAddress((void**)&p_nbr_u, g_nbr_u);
    cudaGetSymbolAddress((void**)&p_off_m, g_off_m);
    cudaGetSymbolAddress((void**)&p_nbr_m, g_nbr_m);

    const int SMEM = (8192 + 2 * 64 * ROWSTRIDE) * 4;  // 67584 bytes
    cudaFuncSetAttribute(sage_fused_kernel, cudaFuncAttributeMaxDynamicSharedMemorySize, SMEM);

    // 0. index dtype detection
    detect_kernel<<<1, 32>>>(edge_src, edge_dst, el_src, el_dst);

    // 1. movie input projection
    xmovie_kernel<<<(M_N * HD + 255) / 256, 256>>>(movie_x, w_movie, b_movie, movie_emb);

    // 2. CSR build (both directions)
    zero_deg_kernel<<<(U_N + 255) / 256, 256>>>();
    hist_kernel<<<1184, 256>>>(edge_src, edge_dst, E);
    scan_both_kernel<<<2, 1024>>>();
    fill_kernel<<<1184, 256>>>(edge_src, edge_dst, E);

    int gu = (U_N + 63) / 64;
    int gm = (M_N + 63) / 64;

    // 3. layer 1 (agg fused into gemm; relu)
    sage_fused_kernel<<<gu, 256, SMEM>>>(p_xmovie, user_emb, p_off_u, p_nbr_u,
                                         l1_rev_Wl, l1_rev_Wr, l1_rev_bl, p_u1, U_N, 1,
                                         nullptr, nullptr, nullptr, 0);
    sage_fused_kernel<<<gm, 256, SMEM>>>(user_emb, p_xmovie, p_off_m, p_nbr_m,
                                         l1_rates_Wl, l1_rates_Wr, l1_rates_bl, p_m1, M_N, 1,
                                         nullptr, nullptr, nullptr, 0);

    // 4. layer 2 (agg fused in; output tile never hits gmem — classifier proj fused in epilogue)
    sage_fused_kernel<<<gu, 256, SMEM>>>(p_m1, p_u1, p_off_u, p_nbr_u,
                                         l2_rev_Wl, l2_rev_Wr, l2_rev_bl, nullptr, U_N, 0,
                                         cls_W, cls_b, p_pu, 0);
    sage_fused_kernel<<<gm, 256, SMEM>>>(p_u1, p_m1, p_off_m, p_nbr_m,
                                         l2_rates_Wl, l2_rates_Wr, l2_rates_bl, nullptr, M_N, 0,
                                         cls_W + 64 * CD, cls_b, p_pm, 1);

    // 5. per-edge gather-add of the two 7-wide projections
    final_kernel<<<(EL * 7 + 255) / 256, 256>>>(el_src, el_dst, out, EL);
}

// round 7
// speedup vs baseline: 1.2144x; 1.0687x over previous
#include <cuda_runtime.h>

// Problem constants (fixed by the dataset)
#define U_N 200000
#define M_N 100000
#define E_MAX 2000000
#define HD 64
#define CD 7
#define ROWSTRIDE 68   // 64 cols padded; multiple of 4 => float4-aligned rows

// ---------------- scratch (device globals; no allocation allowed) ----------------
__device__ float g_xmovie[M_N * HD];
__device__ float g_u1[U_N * HD];
__device__ float g_m1[M_N * HD];
__device__ float g_proj_u[U_N * CD];
__device__ float g_proj_m[M_N * CD];

__device__ int g_deg_u[U_N];
__device__ int g_off_u[U_N + 1];
__device__ int g_cur_u[U_N];
__device__ int g_deg_m[M_N];
__device__ int g_off_m[M_N + 1];
__device__ int g_cur_m[M_N];
__device__ int g_nbr_u[E_MAX];   // movie neighbor per user-grouped edge
__device__ int g_nbr_m[E_MAX];   // user neighbor per movie-grouped edge
__device__ int g_mode[4];        // 1 => indices are int64 on disk, 0 => int32

// ---------------- helpers ----------------
__device__ __forceinline__ int ld_idx(const int* __restrict__ p, int i, int m64) {
    return m64 ? p[2 * i] : p[i];
}

// detect int32/int64 for the 4 index arrays AND zero both degree arrays (merged launch)
__global__ void detect_zero_kernel(const int* es, const int* ed, const int* ls, const int* ld_) {
    int i = blockIdx.x * blockDim.x + threadIdx.x;
    if (i < U_N) g_deg_u[i] = 0;
    if (i < M_N) g_deg_m[i] = 0;
    if (blockIdx.x == 0 && threadIdx.x < 4) {
        int t = threadIdx.x;
        const int* p = (t == 0) ? es : (t == 1) ? ed : (t == 2) ? ls : ld_;
        int o = 0;
#pragma unroll
        for (int k = 0; k < 64; k++) o |= p[2 * k + 1];
        g_mode[t] = (o == 0) ? 1 : 0;
    }
}

__global__ void hist_kernel(const int* __restrict__ es, const int* __restrict__ ed, int E) {
    int m0 = g_mode[0], m1 = g_mode[1];
    for (int i = blockIdx.x * blockDim.x + threadIdx.x; i < E; i += gridDim.x * blockDim.x) {
        atomicAdd(&g_deg_u[ld_idx(es, i, m0)], 1);
        atomicAdd(&g_deg_m[ld_idx(ed, i, m1)], 1);
    }
}

// single-block exclusive scan body; writes cursor copy and off[n] = total
__device__ void scan_body(const int* __restrict__ deg, int* __restrict__ off,
                          int* __restrict__ cur, int n) {
    __shared__ int sh[1024];
    int tid = threadIdx.x;
    int chunk = (n + 1023) >> 10;
    int s0 = tid * chunk;
    int s1 = min(s0 + chunk, n);
    int sum = 0;
    for (int i = s0; i < s1; i++) sum += deg[i];
    sh[tid] = sum;
    __syncthreads();
    for (int d = 1; d < 1024; d <<= 1) {
        int v = (tid >= d) ? sh[tid - d] : 0;
        __syncthreads();
        sh[tid] += v;
        __syncthreads();
    }
    int run = (tid == 0) ? 0 : sh[tid - 1];
    for (int i = s0; i < s1; i++) {
        off[i] = run;
        cur[i] = run;
        run += deg[i];
    }
    if (tid == 0) off[n] = sh[1023];
}

// blocks 0/1: the two scans; blocks >=2: x_movie = movie_x @ w_movie + b + movie_emb
__global__ void scan_xmovie_kernel(const float* __restrict__ mx, const float* __restrict__ w,
                                   const float* __restrict__ b, const float* __restrict__ emb) {
    if (blockIdx.x == 0) { scan_body(g_deg_u, g_off_u, g_cur_u, U_N); return; }
    if (blockIdx.x == 1) { scan_body(g_deg_m, g_off_m, g_cur_m, M_N); return; }
    int idx = (blockIdx.x - 2) * blockDim.x + threadIdx.x;
    if (idx >= M_N * HD) return;
    int m = idx >> 6;
    int h = idx & 63;
    float acc = b[h] + emb[idx];
    const float* xr = mx + m * 20;
#pragma unroll
    for (int f = 0; f < 20; f++) acc = fmaf(xr[f], w[f * 64 + h], acc);
    g_xmovie[idx] = acc;
}

__global__ void fill_kernel(const int* __restrict__ es, const int* __restrict__ ed, int E) {
    int m0 = g_mode[0], m1 = g_mode[1];
    for (int i = blockIdx.x * blockDim.x + threadIdx.x; i < E; i += gridDim.x * blockDim.x) {
        int s = ld_idx(es, i, m0);
        int d = ld_idx(ed, i, m1);
        int pu = atomicAdd(&g_cur_u[s], 1);
        g_nbr_u[pu] = d;
        int pm = atomicAdd(&g_cur_m[d], 1);
        g_nbr_m[pm] = s;
    }
}

// ---------------- fused SAGE layer body ----------------
// One block = 64 nodes x 64 out-cols. Aggregation fused (warp per node, float2 lanes,
// 8-deep unroll). Mainloop k-blocked by 4 with float4 smem loads (LDS-instr bound fix).
// If proj != nullptr: 64x64 tile stays in smem and is projected through clsW (64x7).
__device__ __forceinline__ void sage_body(
    int blk, const float* __restrict__ xsrc, const float* __restrict__ Xroot,
    const int* __restrict__ off, const int* __restrict__ nbr,
    const float* __restrict__ Wl, const float* __restrict__ Wr,
    const float* __restrict__ bias, float* __restrict__ O,
    int N, int do_relu,
    const float* __restrict__ clsW, const float* __restrict__ clsb,
    float* __restrict__ proj, int use_cls_bias) {
    extern __shared__ float sh[];
    float* sWl = sh;                       // 64*64
    float* sWr = sh + 4096;                // 64*64
    float* sA  = sh + 8192;                // 64*68
    float* sX  = sA + 64 * ROWSTRIDE;      // 64*68
    int tid = threadIdx.x;
    int nb = blk * 64;

    // weights -> smem (coalesced float4)
    {
        const float4* wl4 = (const float4*)Wl;
        const float4* wr4 = (const float4*)Wr;
        float4* sl = (float4*)sWl;
        float4* sr = (float4*)sWr;
#pragma unroll
        for (int i = 0; i < 4; i++) {
            sl[tid + 256 * i] = wl4[tid + 256 * i];
            sr[tid + 256 * i] = wr4[tid + 256 * i];
        }
    }

    // ---- fused mean aggregation: warp per node, 8 rounds, float2 per lane ----
    {
        int warp = tid >> 5;
        int lane = tid & 31;
#pragma unroll
        for (int it = 0; it < 8; it++) {
            int r = warp * 8 + it;
            int node = nb + r;
            float a0 = 0.f, a1 = 0.f;
            if (node < N) {
                int s = __ldg(&off[node]);
                int e = __ldg(&off[node + 1]);
                int j = s;
                for (; j + 8 <= e; j += 8) {
                    int n0 = __ldg(&nbr[j]);
                    int n1 = __ldg(&nbr[j + 1]);
                    int n2 = __ldg(&nbr[j + 2]);
                    int n3 = __ldg(&nbr[j + 3]);
                    int n4 = __ldg(&nbr[j + 4]);
                    int n5 = __ldg(&nbr[j + 5]);
                    int n6 = __ldg(&nbr[j + 6]);
                    int n7 = __ldg(&nbr[j + 7]);
                    float2 v0 = ((const float2*)(xsrc + n0 * 64))[lane];
                    float2 v1 = ((const float2*)(xsrc + n1 * 64))[lane];
                    float2 v2 = ((const float2*)(xsrc + n2 * 64))[lane];
                    float2 v3 = ((const float2*)(xsrc + n3 * 64))[lane];
                    float2 v4 = ((const float2*)(xsrc + n4 * 64))[lane];
                    float2 v5 = ((const float2*)(xsrc + n5 * 64))[lane];
                    float2 v6 = ((const float2*)(xsrc + n6 * 64))[lane];
                    float2 v7 = ((const float2*)(xsrc + n7 * 64))[lane];
                    a0 += v0.x + v1.x + v2.x + v3.x + v4.x + v5.x + v6.x + v7.x;
                    a1 += v0.y + v1.y + v2.y + v3.y + v4.y + v5.y + v6.y + v7.y;
                }
                for (; j < e; j++) {
                    float2 v = ((const float2*)(xsrc + __ldg(&nbr[j]) * 64))[lane];
                    a0 += v.x;
                    a1 += v.y;
                }
                float inv = 1.0f / (float)max(e - s, 1);
                a0 *= inv;
                a1 *= inv;
            }
            *(float2*)&sA[r * ROWSTRIDE + lane * 2] = make_float2(a0, a1);
        }
    }

    // ---- root features -> smem (coalesced float4) ----
#pragma unroll
    for (int i = 0; i < 4; i++) {
        int f = tid + 256 * i;       // float4 slot id, 0..1023
        int r = f >> 4;              // row 0..63
        int cc = f & 15;             // float4 col 0..15
        int gr = nb + r;
        float4 vx = make_float4(0.f, 0.f, 0.f, 0.f);
        if (gr < N) vx = ((const float4*)Xroot)[gr * 16 + cc];
        *(float4*)&sX[r * ROWSTRIDE + cc * 4] = vx;
    }
    __syncthreads();

    // ---- mainloop: 4x4 register tile, k blocked by 4, float4 smem loads ----
    int ty = tid >> 4, tx = tid & 15;
    int r0 = ty * 4, c0 = tx * 4;
    float acc[4][4];
#pragma unroll
    for (int i = 0; i < 4; i++)
#pragma unroll
        for (int jj = 0; jj < 4; jj++) acc[i][jj] = 0.f;

#pragma unroll
    for (int kb = 0; kb < 64; kb += 4) {
        float4 A4[4], X4[4];
#pragma unroll
        for (int i = 0; i < 4; i++) {
            A4[i] = *(const float4*)&sA[(r0 + i) * ROWSTRIDE + kb];
            X4[i] = *(const float4*)&sX[(r0 + i) * ROWSTRIDE + kb];
        }
#pragma unroll
        for (int kk = 0; kk < 4; kk++) {
            float4 wl = *(const float4*)&sWl[(kb + kk) * 64 + c0];
            float4 wr = *(const float4*)&sWr[(kb + kk) * 64 + c0];
#pragma unroll
            for (int i = 0; i < 4; i++) {
                float a = ((const float*)&A4[i])[kk];
                float x = ((const float*)&X4[i])[kk];
                acc[i][0] = fmaf(a, wl.x, fmaf(x, wr.x, acc[i][0]));
                acc[i][1] = fmaf(a, wl.y, fmaf(x, wr.y, acc[i][1]));
                acc[i][2] = fmaf(a, wl.z, fmaf(x, wr.z, acc[i][2]));
                acc[i][3] = fmaf(a, wl.w, fmaf(x, wr.w, acc[i][3]));
            }
        }
    }

    float4 bv = *(const float4*)&bias[c0];

    if (proj == nullptr) {
        // layer-1 epilogue: bias (+relu) -> gmem
#pragma unroll
        for (int i = 0; i < 4; i++) {
            int gr = nb + r0 + i;
            if (gr < N) {
                float4 v;
                v.x = acc[i][0] + bv.x;
                v.y = acc[i][1] + bv.y;
                v.z = acc[i][2] + bv.z;
                v.w = acc[i][3] + bv.w;
                if (do_relu) {
                    v.x = fmaxf(v.x, 0.f); v.y = fmaxf(v.y, 0.f);
                    v.z = fmaxf(v.z, 0.f); v.w = fmaxf(v.w, 0.f);
                }
                *(float4*)&O[gr * 64 + c0] = v;
            }
        }
    } else {
        // layer-2 epilogue: biased tile -> smem, fused 64->7 classifier projection
        __syncthreads();   // mainloop reads of sA/sWl complete before overwrite
#pragma unroll
        for (int i = 0; i < 4; i++) {
            float* p = &sA[(r0 + i) * ROWSTRIDE + c0];
            float4 v;
            v.x = acc[i][0] + bv.x;
            v.y = acc[i][1] + bv.y;
            v.z = acc[i][2] + bv.z;
            v.w = acc[i][3] + bv.w;
            *(float4*)p = v;
        }
        for (int i = tid; i < 448; i += 256) sWl[i] = clsW[i];
        __syncthreads();
        for (int o = tid; o < 448; o += 256) {
            int nl = o / 7;
            int c = o - nl * 7;
            int gr = nb + nl;
            if (gr < N) {
                float pacc = use_cls_bias ? clsb[c] : 0.f;
#pragma unroll
                for (int k = 0; k < 64; k++)
                    pacc = fmaf(sA[nl * ROWSTRIDE + k], sWl[k * 7 + c], pacc);
                proj[gr * 7 + c] = pacc;
            }
        }
    }
}

// ---------------- merged per-layer kernels (user blocks then movie blocks) ----------------
__global__ void __launch_bounds__(256, 3) layer1_kernel(
    int guBlocks,
    const float* __restrict__ user_emb,
    const float* __restrict__ Wl_u, const float* __restrict__ Wr_u, const float* __restrict__ b_u,
    const float* __restrict__ Wl_m, const float* __restrict__ Wr_m, const float* __restrict__ b_m) {
    if ((int)blockIdx.x < guBlocks) {
        sage_body(blockIdx.x, g_xmovie, user_emb, g_off_u, g_nbr_u,
                  Wl_u, Wr_u, b_u, g_u1, U_N, 1, nullptr, nullptr, nullptr, 0);
    } else {
        sage_body(blockIdx.x - guBlocks, user_emb, g_xmovie, g_off_m, g_nbr_m,
                  Wl_m, Wr_m, b_m, g_m1, M_N, 1, nullptr, nullptr, nullptr, 0);
    }
}

__global__ void __launch_bounds__(256, 3) layer2_kernel(
    int guBlocks,
    const float* __restrict__ Wl_u, const float* __restrict__ Wr_u, const float* __restrict__ b_u,
    const float* __restrict__ Wl_m, const float* __restrict__ Wr_m, const float* __restrict__ b_m,
    const float* __restrict__ clsW, const float* __restrict__ clsb) {
    if ((int)blockIdx.x < guBlocks) {
        sage_body(blockIdx.x, g_m1, g_u1, g_off_u, g_nbr_u,
                  Wl_u, Wr_u, b_u, nullptr, U_N, 0, clsW, clsb, g_proj_u, 0);
    } else {
        sage_body(blockIdx.x - guBlocks, g_u1, g_m1, g_off_m, g_nbr_m,
                  Wl_m, Wr_m, b_m, nullptr, M_N, 0, clsW + 64 * CD, clsb, g_proj_m, 1);
    }
}

// ---------------- final edge output: out[e][c] = proj_u[src][c] + proj_m[dst][c] ----------------
__global__ void final_kernel(const int* __restrict__ ls, const int* __restrict__ ld_,
                             float* __restrict__ out, int EL) {
    int m2 = g_mode[2], m3 = g_mode[3];
    int total = EL * 7;
    for (int idx = blockIdx.x * blockDim.x + threadIdx.x; idx < total;
         idx += gridDim.x * blockDim.x) {
        int e = idx / 7;
        int c = idx - e * 7;
        int s = ld_idx(ls, e, m2);
        int d = ld_idx(ld_, e, m3);
        out[idx] = g_proj_u[s * 7 + c] + g_proj_m[d * 7 + c];
    }
}

// ---------------- launch ----------------
extern "C" void kernel_launch(void* const* d_in, const int* in_sizes, int n_in,
                              void* d_out, int out_size) {
    const float* movie_x = (const float*)d_in[2];
    const int* edge_src = (const int*)d_in[3];
    const int* edge_dst = (const int*)d_in[4];
    const int* el_src = (const int*)d_in[5];
    const int* el_dst = (const int*)d_in[6];
    const float* user_emb = (const float*)d_in[7];
    const float* movie_emb = (const float*)d_in[8];
    const float* w_movie = (const float*)d_in[9];
    const float* b_movie = (const float*)d_in[10];
    const float* l1_rates_Wl = (const float*)d_in[11];
    const float* l1_rates_bl = (const float*)d_in[12];
    const float* l1_rates_Wr = (const float*)d_in[13];
    const float* l1_rev_Wl = (const float*)d_in[14];
    const float* l1_rev_bl = (const float*)d_in[15];
    const float* l1_rev_Wr = (const float*)d_in[16];
    const float* l2_rates_Wl = (const float*)d_in[17];
    const float* l2_rates_bl = (const float*)d_in[18];
    const float* l2_rates_Wr = (const float*)d_in[19];
    const float* l2_rev_Wl = (const float*)d_in[20];
    const float* l2_rev_bl = (const float*)d_in[21];
    const float* l2_rev_Wr = (const float*)d_in[22];
    const float* cls_W = (const float*)d_in[23];
    const float* cls_b = (const float*)d_in[24];
    float* out = (float*)d_out;

    int E = in_sizes[3];
    if (E > E_MAX) E = E_MAX;
    int EL = out_size / 7;

    const int SMEM = (8192 + 2 * 64 * ROWSTRIDE) * 4;  // 67584 bytes
    cudaFuncSetAttribute(layer1_kernel, cudaFuncAttributeMaxDynamicSharedMemorySize, SMEM);
    cudaFuncSetAttribute(layer2_kernel, cudaFuncAttributeMaxDynamicSharedMemorySize, SMEM);

    int gu = (U_N + 63) / 64;
    int gm = (M_N + 63) / 64;

    // 1. dtype detect + degree zero (merged)
    detect_zero_kernel<<<(U_N + 255) / 256, 256>>>(edge_src, edge_dst, el_src, el_dst);
    // 2. degree histogram
    hist_kernel<<<1184, 256>>>(edge_src, edge_dst, E);
    // 3. offsets scan (blocks 0-1) + movie input projection (rest), independent work merged
    scan_xmovie_kernel<<<2 + (M_N * HD + 1023) / 1024, 1024>>>(movie_x, w_movie, b_movie, movie_emb);
    // 4. CSR fill (both directions)
    fill_kernel<<<1184, 256>>>(edge_src, edge_dst, E);

    // 5. layer 1 (agg fused into gemm; relu) — both directions in one grid
    layer1_kernel<<<gu + gm, 256, SMEM>>>(gu, user_emb,
                                          l1_rev_Wl, l1_rev_Wr, l1_rev_bl,
                                          l1_rates_Wl, l1_rates_Wr, l1_rates_bl);
    // 6. layer 2 + fused classifier projection — both directions in one grid
    layer2_kernel<<<gu + gm, 256, SMEM>>>(gu,
                                          l2_rev_Wl, l2_rev_Wr, l2_rev_bl,
                                          l2_rates_Wl, l2_rates_Wr, l2_rates_bl,
                                          cls_W, cls_b);
    // 7. per-edge gather-add of the two 7-wide projections
    final_kernel<<<(EL * 7 + 255) / 256, 256>>>(el_src, el_dst, out, EL);
}

// round 11
// speedup vs baseline: 1.4916x; 1.2282x over previous
#include <cuda_runtime.h>

// Problem constants (fixed by the dataset)
#define U_N 200000
#define M_N 100000
#define E_MAX 2000000
#define HD 64
#define CD 7
#define ROWSTRIDE 68   // 64 cols padded; multiple of 4 => float4-aligned rows

// ---------------- scratch (device globals; no allocation allowed) ----------------
__device__ float g_xmovie[M_N * HD];
__device__ float g_u1p[U_N * 16];   // per user: [0:7] root-proj (u1@R2u), [8:15] agg-proj (u1@A2m)
__device__ float g_m1p[M_N * 16];   // per movie: [0:7] root-proj (m1@R2m), [8:15] agg-proj (m1@A2u)
__device__ float g_proj_u[U_N * CD];
__device__ float g_proj_m[M_N * CD];

// folded layer2+classifier matrices (64x7 each) and bias vectors
__device__ float g_A2u[448];   // l2_rev_Wl   @ clsW_u
__device__ float g_R2u[448];   // l2_rev_Wr   @ clsW_u
__device__ float g_A2m[448];   // l2_rates_Wl @ clsW_m
__device__ float g_R2m[448];   // l2_rates_Wr @ clsW_m
__device__ float g_cu[7];      // l2_rev_bl   @ clsW_u
__device__ float g_cm[7];      // l2_rates_bl @ clsW_m + clsb

__device__ int g_deg_u[U_N];
__device__ int g_off_u[U_N + 1];
__device__ int g_cur_u[U_N];
__device__ int g_deg_m[M_N];
__device__ int g_off_m[M_N + 1];
__device__ int g_cur_m[M_N];
__device__ int g_nbr_u[E_MAX];   // movie neighbor per user-grouped edge
__device__ int g_nbr_m[E_MAX];   // user neighbor per movie-grouped edge
__device__ int g_mode[4];        // 1 => indices are int64 on disk, 0 => int32

// ---------------- helpers ----------------
__device__ __forceinline__ int ld_idx(const int* __restrict__ p, int i, int m64) {
    return m64 ? p[2 * i] : p[i];
}

// detect int32/int64 for the 4 index arrays AND zero both degree arrays (merged launch)
__global__ void detect_zero_kernel(const int* es, const int* ed, const int* ls, const int* ld_) {
    int i = blockIdx.x * blockDim.x + threadIdx.x;
    if (i < U_N) g_deg_u[i] = 0;
    if (i < M_N) g_deg_m[i] = 0;
    if (blockIdx.x == 0 && threadIdx.x < 4) {
        int t = threadIdx.x;
        const int* p = (t == 0) ? es : (t == 1) ? ed : (t == 2) ? ls : ld_;
        int o = 0;
#pragma unroll
        for (int k = 0; k < 64; k++) o |= p[2 * k + 1];
        g_mode[t] = (o == 0) ? 1 : 0;
    }
}

// fold layer-2 weights through the classifier: A2u/R2u/A2m/R2m (64x7), c_u/c_m (7)
__global__ void combine_kernel(const float* __restrict__ l2rev_Wl, const float* __restrict__ l2rev_Wr,
                               const float* __restrict__ l2rev_bl,
                               const float* __restrict__ l2rates_Wl, const float* __restrict__ l2rates_Wr,
                               const float* __restrict__ l2rates_bl,
                               const float* __restrict__ clsW, const float* __restrict__ clsb) {
    int o = threadIdx.x;
    if (o < 448) {
        int k = o / 7, c = o - (o / 7) * 7;
        float a2u = 0.f, r2u = 0.f, a2m = 0.f, r2m = 0.f;
#pragma unroll
        for (int j = 0; j < 64; j++) {
            float wu = clsW[j * 7 + c];          // user half of cls_W (rows 0..63)
            float wm = clsW[(64 + j) * 7 + c];   // movie half (rows 64..127)
            a2u = fmaf(l2rev_Wl[k * 64 + j], wu, a2u);
            r2u = fmaf(l2rev_Wr[k * 64 + j], wu, r2u);
            a2m = fmaf(l2rates_Wl[k * 64 + j], wm, a2m);
            r2m = fmaf(l2rates_Wr[k * 64 + j], wm, r2m);
        }
        g_A2u[o] = a2u; g_R2u[o] = r2u; g_A2m[o] = a2m; g_R2m[o] = r2m;
    } else if (o < 455) {
        int c = o - 448;
        float cu = 0.f, cm = 0.f;
#pragma unroll
        for (int j = 0; j < 64; j++) {
            cu = fmaf(l2rev_bl[j], clsW[j * 7 + c], cu);
            cm = fmaf(l2rates_bl[j], clsW[(64 + j) * 7 + c], cm);
        }
        g_cu[c] = cu;
        g_cm[c] = cm + clsb[c];
    }
}

__global__ void hist_kernel(const int* __restrict__ es, const int* __restrict__ ed, int E) {
    int m0 = g_mode[0], m1 = g_mode[1];
    for (int i = blockIdx.x * blockDim.x + threadIdx.x; i < E; i += gridDim.x * blockDim.x) {
        atomicAdd(&g_deg_u[ld_idx(es, i, m0)], 1);
        atomicAdd(&g_deg_m[ld_idx(ed, i, m1)], 1);
    }
}

// single-block exclusive scan body; writes cursor copy and off[n] = total
__device__ void scan_body(const int* __restrict__ deg, int* __restrict__ off,
                          int* __restrict__ cur, int n) {
    __shared__ int sh[1024];
    int tid = threadIdx.x;
    int chunk = (n + 1023) >> 10;
    int s0 = tid * chunk;
    int s1 = min(s0 + chunk, n);
    int sum = 0;
    for (int i = s0; i < s1; i++) sum += deg[i];
    sh[tid] = sum;
    __syncthreads();
    for (int d = 1; d < 1024; d <<= 1) {
        int v = (tid >= d) ? sh[tid - d] : 0;
        __syncthreads();
        sh[tid] += v;
        __syncthreads();
    }
    int run = (tid == 0) ? 0 : sh[tid - 1];
    for (int i = s0; i < s1; i++) {
        off[i] = run;
        cur[i] = run;
        run += deg[i];
    }
    if (tid == 0) off[n] = sh[1023];
}

// blocks 0/1: the two scans; blocks >=2: x_movie = movie_x @ w_movie + b + movie_emb
__global__ void scan_xmovie_kernel(const float* __restrict__ mx, const float* __restrict__ w,
                                   const float* __restrict__ b, const float* __restrict__ emb) {
    if (blockIdx.x == 0) { scan_body(g_deg_u, g_off_u, g_cur_u, U_N); return; }
    if (blockIdx.x == 1) { scan_body(g_deg_m, g_off_m, g_cur_m, M_N); return; }
    int idx = (blockIdx.x - 2) * blockDim.x + threadIdx.x;
    if (idx >= M_N * HD) return;
    int m = idx >> 6;
    int h = idx & 63;
    float acc = b[h] + emb[idx];
    const float* xr = mx + m * 20;
#pragma unroll
    for (int f = 0; f < 20; f++) acc = fmaf(xr[f], w[f * 64 + h], acc);
    g_xmovie[idx] = acc;
}

__global__ void fill_kernel(const int* __restrict__ es, const int* __restrict__ ed, int E) {
    int m0 = g_mode[0], m1 = g_mode[1];
    for (int i = blockIdx.x * blockDim.x + threadIdx.x; i < E; i += gridDim.x * blockDim.x) {
        int s = ld_idx(es, i, m0);
        int d = ld_idx(ed, i, m1);
        int pu = atomicAdd(&g_cur_u[s], 1);
        g_nbr_u[pu] = d;
        int pm = atomicAdd(&g_cur_m[d], 1);
        g_nbr_m[pm] = s;
    }
}

// ---------------- fused SAGE layer-1 body ----------------
// One block = 64 nodes. Fused: mean-agg gather -> dual-weight GEMM -> bias -> relu ->
// dual 64->7 projection through folded layer-2 matrices (root & agg slots of dst).
// The 64-wide hidden state never touches gmem.
__device__ __forceinline__ void sage_body(
    int blk, const float* __restrict__ xsrc, const float* __restrict__ Xroot,
    const int* __restrict__ off, const int* __restrict__ nbr,
    const float* __restrict__ Wl, const float* __restrict__ Wr,
    const float* __restrict__ bias, int N,
    const float* __restrict__ Rmat, const float* __restrict__ Amat,
    float* __restrict__ dst) {
    extern __shared__ float sh[];
    float* sWl = sh;                       // 64*64
    float* sWr = sh + 4096;                // 64*64
    float* sA  = sh + 8192;                // 64*68
    float* sX  = sA + 64 * ROWSTRIDE;      // 64*68
    int tid = threadIdx.x;
    int nb = blk * 64;

    // weights -> smem (coalesced float4)
    {
        const float4* wl4 = (const float4*)Wl;
        const float4* wr4 = (const float4*)Wr;
        float4* sl = (float4*)sWl;
        float4* sr = (float4*)sWr;
#pragma unroll
        for (int i = 0; i < 4; i++) {
            sl[tid + 256 * i] = wl4[tid + 256 * i];
            sr[tid + 256 * i] = wr4[tid + 256 * i];
        }
    }

    // ---- fused mean aggregation: warp per node, 8 rounds, float2 per lane ----
    {
        int warp = tid >> 5;
        int lane = tid & 31;
#pragma unroll
        for (int it = 0; it < 8; it++) {
            int r = warp * 8 + it;
            int node = nb + r;
            float a0 = 0.f, a1 = 0.f;
            if (node < N) {
                int s = __ldg(&off[node]);
                int e = __ldg(&off[node + 1]);
                int j = s;
                for (; j + 8 <= e; j += 8) {
                    int n0 = __ldg(&nbr[j]);
                    int n1 = __ldg(&nbr[j + 1]);
                    int n2 = __ldg(&nbr[j + 2]);
                    int n3 = __ldg(&nbr[j + 3]);
                    int n4 = __ldg(&nbr[j + 4]);
                    int n5 = __ldg(&nbr[j + 5]);
                    int n6 = __ldg(&nbr[j + 6]);
                    int n7 = __ldg(&nbr[j + 7]);
                    float2 v0 = ((const float2*)(xsrc + n0 * 64))[lane];
                    float2 v1 = ((const float2*)(xsrc + n1 * 64))[lane];
                    float2 v2 = ((const float2*)(xsrc + n2 * 64))[lane];
                    float2 v3 = ((const float2*)(xsrc + n3 * 64))[lane];
                    float2 v4 = ((const float2*)(xsrc + n4 * 64))[lane];
                    float2 v5 = ((const float2*)(xsrc + n5 * 64))[lane];
                    float2 v6 = ((const float2*)(xsrc + n6 * 64))[lane];
                    float2 v7 = ((const float2*)(xsrc + n7 * 64))[lane];
                    a0 += v0.x + v1.x + v2.x + v3.x + v4.x + v5.x + v6.x + v7.x;
                    a1 += v0.y + v1.y + v2.y + v3.y + v4.y + v5.y + v6.y + v7.y;
                }
                for (; j < e; j++) {
                    float2 v = ((const float2*)(xsrc + __ldg(&nbr[j]) * 64))[lane];
                    a0 += v.x;
                    a1 += v.y;
                }
                float inv = 1.0f / (float)max(e - s, 1);
                a0 *= inv;
                a1 *= inv;
            }
            *(float2*)&sA[r * ROWSTRIDE + lane * 2] = make_float2(a0, a1);
        }
    }

    // ---- root features -> smem (coalesced float4) ----
#pragma unroll
    for (int i = 0; i < 4; i++) {
        int f = tid + 256 * i;       // float4 slot id, 0..1023
        int r = f >> 4;              // row 0..63
        int cc = f & 15;             // float4 col 0..15
        int gr = nb + r;
        float4 vx = make_float4(0.f, 0.f, 0.f, 0.f);
        if (gr < N) vx = ((const float4*)Xroot)[gr * 16 + cc];
        *(float4*)&sX[r * ROWSTRIDE + cc * 4] = vx;
    }
    __syncthreads();

    // ---- mainloop: 4x4 register tile, k blocked by 4, float4 smem loads ----
    int ty = tid >> 4, tx = tid & 15;
    int r0 = ty * 4, c0 = tx * 4;
    float acc[4][4];
#pragma unroll
    for (int i = 0; i < 4; i++)
#pragma unroll
        for (int jj = 0; jj < 4; jj++) acc[i][jj] = 0.f;

#pragma unroll
    for (int kb = 0; kb < 64; kb += 4) {
        float4 A4[4], X4[4];
#pragma unroll
        for (int i = 0; i < 4; i++) {
            A4[i] = *(const float4*)&sA[(r0 + i) * ROWSTRIDE + kb];
            X4[i] = *(const float4*)&sX[(r0 + i) * ROWSTRIDE + kb];
        }
#pragma unroll
        for (int kk = 0; kk < 4; kk++) {
            float4 wl = *(const float4*)&sWl[(kb + kk) * 64 + c0];
            float4 wr = *(const float4*)&sWr[(kb + kk) * 64 + c0];
#pragma unroll
            for (int i = 0; i < 4; i++) {
                float a = ((const float*)&A4[i])[kk];
                float x = ((const float*)&X4[i])[kk];
                acc[i][0] = fmaf(a, wl.x, fmaf(x, wr.x, acc[i][0]));
                acc[i][1] = fmaf(a, wl.y, fmaf(x, wr.y, acc[i][1]));
                acc[i][2] = fmaf(a, wl.z, fmaf(x, wr.z, acc[i][2]));
                acc[i][3] = fmaf(a, wl.w, fmaf(x, wr.w, acc[i][3]));
            }
        }
    }

    float4 bv = *(const float4*)&bias[c0];

    // ---- epilogue: bias + relu tile -> smem, dual 64->7 projection -> dst ----
    __syncthreads();   // all mainloop smem reads complete before overwrite
#pragma unroll
    for (int i = 0; i < 4; i++) {
        float4 v;
        v.x = fmaxf(acc[i][0] + bv.x, 0.f);
        v.y = fmaxf(acc[i][1] + bv.y, 0.f);
        v.z = fmaxf(acc[i][2] + bv.z, 0.f);
        v.w = fmaxf(acc[i][3] + bv.w, 0.f);
        *(float4*)&sA[(r0 + i) * ROWSTRIDE + c0] = v;
    }
    // folded projection matrices: R in sWl[0:448], A in sWl[448:896]
    for (int i2 = tid; i2 < 896; i2 += 256)
        sWl[i2] = (i2 < 448) ? Rmat[i2] : Amat[i2 - 448];
    __syncthreads();
    for (int o = tid; o < 448; o += 256) {
        int nl = o / 7;
        int c = o - nl * 7;
        int gr = nb + nl;
        if (gr < N) {
            float r = 0.f, a = 0.f;
#pragma unroll
            for (int k = 0; k < 64; k++) {
                float v = sA[nl * ROWSTRIDE + k];
                r = fmaf(v, sWl[k * 7 + c], r);
                a = fmaf(v, sWl[448 + k * 7 + c], a);
            }
            dst[gr * 16 + c] = r;        // root slot
            dst[gr * 16 + 8 + c] = a;    // agg slot
        }
    }
}

// user blocks then movie blocks in one grid
__global__ void __launch_bounds__(256, 3) layer1_kernel(
    int guBlocks,
    const float* __restrict__ user_emb,
    const float* __restrict__ Wl_u, const float* __restrict__ Wr_u, const float* __restrict__ b_u,
    const float* __restrict__ Wl_m, const float* __restrict__ Wr_m, const float* __restrict__ b_m) {
    if ((int)blockIdx.x < guBlocks) {
        sage_body(blockIdx.x, g_xmovie, user_emb, g_off_u, g_nbr_u,
                  Wl_u, Wr_u, b_u, U_N, g_R2u, g_A2m, g_u1p);
    } else {
        sage_body(blockIdx.x - guBlocks, user_emb, g_xmovie, g_off_m, g_nbr_m,
                  Wl_m, Wr_m, b_m, M_N, g_R2m, g_A2u, g_m1p);
    }
}

// ---------------- layer 2 (7-wide): proj = mean-agg(peer agg-proj) + own root-proj + c ----------------
// Half-warp per node: lanes {0..6} and {16..22} each own one node's 7 channels.
__global__ void proj_agg_kernel() {
    int w = (blockIdx.x * blockDim.x + threadIdx.x) >> 5;
    int lane = threadIdx.x & 31;
    int half = lane >> 4;
    int c = lane & 15;
    int gnode = w * 2 + half;
    if (c >= 7 || gnode >= U_N + M_N) return;
    bool isU = gnode < U_N;
    int node = isU ? gnode : gnode - U_N;
    const int* off = isU ? g_off_u : g_off_m;
    const int* nbr = isU ? g_nbr_u : g_nbr_m;
    const float* srcp = isU ? g_m1p : g_u1p;    // aggregate peer's agg-proj slot
    const float* rootp = isU ? g_u1p : g_m1p;   // own root-proj slot
    const float* cv = isU ? g_cu : g_cm;
    float* dst = isU ? g_proj_u : g_proj_m;

    int s = __ldg(&off[node]);
    int e = __ldg(&off[node + 1]);
    float sum = 0.f;
    int j = s;
    for (; j + 4 <= e; j += 4) {
        int n0 = __ldg(&nbr[j]);
        int n1 = __ldg(&nbr[j + 1]);
        int n2 = __ldg(&nbr[j + 2]);
        int n3 = __ldg(&nbr[j + 3]);
        sum += srcp[n0 * 16 + 8 + c] + srcp[n1 * 16 + 8 + c] +
               srcp[n2 * 16 + 8 + c] + srcp[n3 * 16 + 8 + c];
    }
    for (; j < e; j++) sum += srcp[__ldg(&nbr[j]) * 16 + 8 + c];
    float inv = 1.0f / (float)max(e - s, 1);
    dst[node * 7 + c] = sum * inv + rootp[node * 16 + c] + cv[c];
}

// ---------------- final edge output: out[e][c] = proj_u[src][c] + proj_m[dst][c] ----------------
__global__ void final_kernel(const int* __restrict__ ls, const int* __restrict__ ld_,
                             float* __restrict__ out, int EL) {
    int m2 = g_mode[2], m3 = g_mode[3];
    int total = EL * 7;
    for (int idx = blockIdx.x * blockDim.x + threadIdx.x; idx < total;
         idx += gridDim.x * blockDim.x) {
        int e = idx / 7;
        int c = idx - e * 7;
        int s = ld_idx(ls, e, m2);
        int d = ld_idx(ld_, e, m3);
        out[idx] = g_proj_u[s * 7 + c] + g_proj_m[d * 7 + c];
    }
}

// ---------------- launch ----------------
extern "C" void kernel_launch(void* const* d_in, const int* in_sizes, int n_in,
                              void* d_out, int out_size) {
    const float* movie_x = (const float*)d_in[2];
    const int* edge_src = (const int*)d_in[3];
    const int* edge_dst = (const int*)d_in[4];
    const int* el_src = (const int*)d_in[5];
    const int* el_dst = (const int*)d_in[6];
    const float* user_emb = (const float*)d_in[7];
    const float* movie_emb = (const float*)d_in[8];
    const float* w_movie = (const float*)d_in[9];
    const float* b_movie = (const float*)d_in[10];
    const float* l1_rates_Wl = (const float*)d_in[11];
    const float* l1_rates_bl = (const float*)d_in[12];
    const float* l1_rates_Wr = (const float*)d_in[13];
    const float* l1_rev_Wl = (const float*)d_in[14];
    const float* l1_rev_bl = (const float*)d_in[15];
    const float* l1_rev_Wr = (const float*)d_in[16];
    const float* l2_rates_Wl = (const float*)d_in[17];
    const float* l2_rates_bl = (const float*)d_in[18];
    const float* l2_rates_Wr = (const float*)d_in[19];
    const float* l2_rev_Wl = (const float*)d_in[20];
    const float* l2_rev_bl = (const float*)d_in[21];
    const float* l2_rev_Wr = (const float*)d_in[22];
    const float* cls_W = (const float*)d_in[23];
    const float* cls_b = (const float*)d_in[24];
    float* out = (float*)d_out;

    int E = in_sizes[3];
    if (E > E_MAX) E = E_MAX;
    int EL = out_size / 7;

    const int SMEM = (8192 + 2 * 64 * ROWSTRIDE) * 4;  // 67584 bytes
    cudaFuncSetAttribute(layer1_kernel, cudaFuncAttributeMaxDynamicSharedMemorySize, SMEM);

    int gu = (U_N + 63) / 64;
    int gm = (M_N + 63) / 64;

    // 1. dtype detect + degree zero (merged)
    detect_zero_kernel<<<(U_N + 255) / 256, 256>>>(edge_src, edge_dst, el_src, el_dst);
    // 2. fold layer-2 weights through classifier (tiny, independent)
    combine_kernel<<<1, 512>>>(l2_rev_Wl, l2_rev_Wr, l2_rev_bl,
                               l2_rates_Wl, l2_rates_Wr, l2_rates_bl, cls_W, cls_b);
    // 3. degree histogram
    hist_kernel<<<1184, 256>>>(edge_src, edge_dst, E);
    // 4. offsets scan (blocks 0-1) + movie input projection (rest)
    scan_xmovie_kernel<<<2 + (M_N * HD + 1023) / 1024, 1024>>>(movie_x, w_movie, b_movie, movie_emb);
    // 5. CSR fill (both directions)
    fill_kernel<<<1184, 256>>>(edge_src, edge_dst, E);

    // 6. layer 1: fused agg + GEMM + relu + dual 64->7 projection (both directions, one grid)
    layer1_kernel<<<gu + gm, 256, SMEM>>>(gu, user_emb,
                                          l1_rev_Wl, l1_rev_Wr, l1_rev_bl,
                                          l1_rates_Wl, l1_rates_Wr, l1_rates_bl);
    // 7. layer 2 collapsed to 7-wide mean gather + root add (both directions, one grid)
    {
        int warps = (U_N + M_N + 1) / 2;          // half-warp per node
        int blocks = (warps * 32 + 255) / 256;
        proj_agg_kernel<<<blocks, 256>>>();
    }
    // 8. per-edge gather-add of the two 7-wide projections
    final_kernel<<<(EL * 7 + 255) / 256, 256>>>(el_src, el_dst, out, EL);
}